// round 7
// baseline (speedup 1.0000x reference)
#include <cuda_runtime.h>
#include <math.h>

// Problem constants
#define Bb 4
#define Nn 16
#define Gg 64            // Bb*Nn
#define Ll 2048
#define Ee 32768
#define C0 64
#define Cc 128
#define C2 256
#define EPSf 1e-5

// ---------------- scratch (static device globals; no allocation) ----------------
__device__ float g_h0  [Gg*Ll*C0];   // transposed x        [g,l,64]
__device__ float g_agg0[Gg*Ll*C0];   // A @ h0              [g,l,64]
__device__ float g_hW  [Gg*Ll*Cc];   // GEMM out pre-agg    [g,l,128]
__device__ float g_a   [Gg*Ll*Cc];   // post-agg (+bias)    [g,l,128]
__device__ float g_hlow[Gg*Ll*Cc];   // activated lower     [g,l,128]
__device__ float g_hup [Bb*Ll*Cc];   // activated amax part [b,l,128]
__device__ float g_U   [Bb*Ll*Cc];   // hup @ W_up          [b,l,128]
__device__ float g_amax[Bb*Ll*Cc];   // max over n of a     [b,l,128]

__device__ double g_sum[C2], g_sumsq[C2];
__device__ float  g_scale[C2], g_shift[C2];

__device__ int   g_cnt[Ll], g_cnt2[Ll];
__device__ int   g_rowptr[Ll+1];
__device__ int   g_col[Ee];
__device__ float g_enorm[Ee];
__device__ float g_dinv[Ll], g_selfnorm[Ll];
__device__ int   g_is64;   // 1 if edge_index buffer holds int64, 0 if int32

// ---------------- edge dtype detection + safe accessor ----------------
// JAX silently downcasts int64->int32 unless x64 is enabled; detect on device.
// Under an int64 layout with values < 2048, all odd 32-bit words are zero.
// Under int32, odd words are random node ids -> some nonzero (P(all 0) ~ 0).
__global__ void detect_dtype(const unsigned int* __restrict__ w) {
    __shared__ int any;
    if (threadIdx.x == 0) any = 0;
    __syncthreads();
    // Only inspect the first 16384 words: safe under either layout
    // (int32 buffer has 65536 words; int64 buffer has 131072).
    for (int i = 2 * threadIdx.x + 1; i < 16384; i += 2 * blockDim.x)
        if (w[i] != 0u) any = 1;
    __syncthreads();
    if (threadIdx.x == 0) g_is64 = (any == 0) ? 1 : 0;
}

__device__ __forceinline__ int edge_at(const void* __restrict__ ei, int idx) {
    int v;
    if (g_is64) v = (int)(((const long long*)ei)[idx]);
    else        v = ((const int*)ei)[idx];
    return v & (Ll - 1);   // defensive mask; no-op for valid data (Ll = 2048)
}

// ---------------- graph structure build ----------------
__global__ void zero_counts() {
    int i = blockIdx.x * blockDim.x + threadIdx.x;
    if (i < Ll) { g_cnt[i] = 0; g_cnt2[i] = 0; }
}

__global__ void count_edges(const void* __restrict__ ei) {
    int e = blockIdx.x * blockDim.x + threadIdx.x;
    if (e < Ee) atomicAdd(&g_cnt[edge_at(ei, Ee + e)], 1);
}

// one block, 256 threads: exclusive scan of g_cnt -> g_rowptr, plus dinv/selfnorm
__global__ void scan_build() {
    __shared__ int part[257];
    const int CH = Ll / 256;  // 8
    int tid = threadIdx.x;
    int base = tid * CH;
    int vals[CH];
    int s = 0;
    #pragma unroll
    for (int i = 0; i < CH; i++) { vals[i] = g_cnt[base + i]; s += vals[i]; }
    part[tid + 1] = s;
    if (tid == 0) part[0] = 0;
    __syncthreads();
    if (tid == 0) { for (int i = 1; i <= 256; i++) part[i] += part[i - 1]; }
    __syncthreads();
    int run = part[tid];
    #pragma unroll
    for (int i = 0; i < CH; i++) {
        g_rowptr[base + i] = run; run += vals[i];
        float deg = (float)vals[i] + 2.0f;          // self loop weight 2
        g_dinv[base + i] = rsqrtf(deg);
        g_selfnorm[base + i] = 2.0f / deg;          // 2 * dinv^2
    }
    if (tid == 255) g_rowptr[Ll] = run;
}

__global__ void fill_edges(const void* __restrict__ ei) {
    int e = blockIdx.x * blockDim.x + threadIdx.x;
    if (e < Ee) {
        int s = edge_at(ei, e);
        int d = edge_at(ei, Ee + e);
        int pos = g_rowptr[d] + atomicAdd(&g_cnt2[d], 1);
        g_col[pos] = s;
        g_enorm[pos] = g_dinv[s] * g_dinv[d];
    }
}

// ---------------- transpose x [b,n,c,l] -> g_h0 [g,l,c] ----------------
__global__ void transpose_x(const float* __restrict__ x) {
    __shared__ float t[32][33];
    int g = blockIdx.z, c0 = blockIdx.y * 32, l0 = blockIdx.x * 32;
    int tx = threadIdx.x, ty = threadIdx.y;
    #pragma unroll
    for (int i = 0; i < 32; i += 8) {
        int c = c0 + ty + i, l = l0 + tx;
        t[ty + i][tx] = x[((size_t)(g * C0 + c)) * Ll + l];
    }
    __syncthreads();
    #pragma unroll
    for (int i = 0; i < 32; i += 8) {
        int l = l0 + ty + i, c = c0 + tx;
        g_h0[((size_t)g * Ll + l) * C0 + c] = t[tx][ty + i];
    }
}

// ---------------- GEMM body: Y[row, 0..127] = X[row, 0..K-1] @ W[K,128] (+U)(+bias) ----------------
template <int K, bool ADD_U, bool ADD_BIAS>
__device__ __forceinline__ void gemm_body(
    const float* __restrict__ X, const float* __restrict__ W,
    const float* __restrict__ bias, const float* __restrict__ U,
    float* __restrict__ Y)
{
    __shared__ __align__(16) float sX[32 * K];
    int tid = threadIdx.x;
    size_t row0 = (size_t)blockIdx.x * 32;

    const float4* Xv = (const float4*)(X + row0 * K);
    float4* sv = (float4*)sX;
    #pragma unroll
    for (int i = tid; i < 32 * K / 4; i += 128) sv[i] = Xv[i];
    __syncthreads();

    float acc[32];
    #pragma unroll
    for (int r = 0; r < 32; r++) acc[r] = 0.f;

    for (int k = 0; k < K; k += 4) {
        float w0 = W[(k + 0) * 128 + tid];
        float w1 = W[(k + 1) * 128 + tid];
        float w2 = W[(k + 2) * 128 + tid];
        float w3 = W[(k + 3) * 128 + tid];
        #pragma unroll
        for (int r = 0; r < 32; r++) {
            float4 xv = *(const float4*)(sX + r * K + k);
            acc[r] = fmaf(xv.x, w0, fmaf(xv.y, w1, fmaf(xv.z, w2, fmaf(xv.w, w3, acc[r]))));
        }
    }

    float bv = ADD_BIAS ? bias[tid] : 0.f;
    #pragma unroll
    for (int r = 0; r < 32; r++) {
        size_t row = row0 + r;
        float v = acc[r] + bv;
        if (ADD_U) {
            size_t l = row % Ll;
            size_t b = row / ((size_t)Nn * Ll);
            v += U[(b * Ll + l) * Cc + tid];
        }
        Y[row * Cc + tid] = v;
    }
}

__global__ __launch_bounds__(128) void gemm1_kernel(const float* __restrict__ W, const float* __restrict__ bias) {
    gemm_body<C0, false, true>(g_agg0, W, bias, nullptr, g_a);
}
__global__ __launch_bounds__(128) void gemmU_kernel(const float* __restrict__ Wup) {
    gemm_body<Cc, false, false>(g_hup, Wup, nullptr, nullptr, g_U);
}
__global__ __launch_bounds__(128) void gemmM_kernel(const float* __restrict__ Wlow) {
    gemm_body<Cc, true, false>(g_hlow, Wlow, nullptr, g_U, g_hW);
}

// ---------------- aggregation: Y[g,dst,:] = selfnorm*X[g,dst,:] + sum_e norm*X[g,src,:] (+bias) ----------------
template <int C, bool ADD_BIAS>
__device__ __forceinline__ void agg_body(
    const float* __restrict__ Xin, const float* __restrict__ bias, float* __restrict__ Yout)
{
    constexpr int TPN = C / 4;
    constexpr int NPB = 128 / TPN;
    int lane = threadIdx.x % TPN;
    int nidx = threadIdx.x / TPN;
    size_t ng = (size_t)blockIdx.x * NPB + nidx;     // over G*L
    int node = (int)(ng % Ll);
    size_t g = ng / Ll;
    const float4* Xg = (const float4*)(Xin + g * Ll * C);

    float sn = g_selfnorm[node];
    float4 xv = Xg[(size_t)node * TPN + lane];
    float4 acc = make_float4(sn * xv.x, sn * xv.y, sn * xv.z, sn * xv.w);

    int s = g_rowptr[node], e = g_rowptr[node + 1];
    for (int i = s; i < e; i++) {
        float nw = g_enorm[i];
        float4 v = Xg[(size_t)g_col[i] * TPN + lane];
        acc.x += nw * v.x; acc.y += nw * v.y; acc.z += nw * v.z; acc.w += nw * v.w;
    }
    if (ADD_BIAS) {
        float4 bv = ((const float4*)bias)[lane];
        acc.x += bv.x; acc.y += bv.y; acc.z += bv.z; acc.w += bv.w;
    }
    ((float4*)Yout)[ng * TPN + lane] = acc;
}

__global__ __launch_bounds__(128) void agg1_kernel() {
    agg_body<C0, false>(g_h0, nullptr, g_agg0);
}
__global__ __launch_bounds__(128) void agg2_kernel(const float* __restrict__ bias) {
    agg_body<Cc, true>(g_hW, bias, g_a);
}

// ---------------- amax over n ----------------
__global__ void amax_kernel() {
    int tid = threadIdx.x;                 // channel
    size_t bl = blockIdx.x;                // over B*L
    size_t b = bl / Ll, l = bl % Ll;
    float m = -3.4e38f;
    #pragma unroll
    for (int n = 0; n < Nn; n++)
        m = fmaxf(m, g_a[(((b * Nn + n) * Ll) + l) * Cc + tid]);
    g_amax[bl * Cc + tid] = m;
}

// ---------------- BN stats ----------------
__global__ void zero_stats() {
    int i = threadIdx.x;
    g_sum[i] = 0.0; g_sumsq[i] = 0.0;
}

__global__ void stats_a_kernel() {
    int c = threadIdx.x;                       // 128
    const size_t rows = (size_t)Gg * Ll;       // 131072
    size_t per = rows / gridDim.x;
    size_t r0 = (size_t)blockIdx.x * per;
    float s = 0.f, ss = 0.f;
    for (size_t r = r0; r < r0 + per; r++) {
        float v = g_a[r * Cc + c];
        s += v; ss += v * v;
    }
    atomicAdd(&g_sum[c], (double)s);
    atomicAdd(&g_sumsq[c], (double)ss);
}

__global__ void stats_amax_kernel() {
    int c = threadIdx.x;
    const size_t rows = (size_t)Bb * Ll;       // 8192
    size_t per = rows / gridDim.x;
    size_t r0 = (size_t)blockIdx.x * per;
    float s = 0.f, ss = 0.f;
    for (size_t r = r0; r < r0 + per; r++) {
        float v = g_amax[r * Cc + c];
        s += v; ss += v * v;
    }
    atomicAdd(&g_sum[Cc + c], (double)s);
    atomicAdd(&g_sumsq[Cc + c], (double)ss);
}

__global__ void bn_kernel(const float* __restrict__ gamma, const float* __restrict__ beta) {
    int c = threadIdx.x;                       // 256
    double cnt = (c < Cc) ? (double)((size_t)Gg * Ll) : (double)((size_t)Bb * Ll);
    double mean = g_sum[c] / cnt;
    double var  = g_sumsq[c] / cnt - mean * mean;
    double inv  = 1.0 / sqrt(var + (double)EPSf);
    double sc   = (double)gamma[c] * inv;
    g_scale[c] = (float)sc;
    g_shift[c] = (float)((double)beta[c] - mean * sc);
}

// ---------------- activations ----------------
__global__ void act_low_kernel() {
    int i = blockIdx.x * blockDim.x + threadIdx.x;    // G*L*128
    int c = i & (Cc - 1);
    g_hlow[i] = fmaxf(0.f, fmaf(g_a[i], g_scale[c], g_shift[c]));
}
__global__ void act_up_kernel() {
    int i = blockIdx.x * blockDim.x + threadIdx.x;    // B*L*128
    int c = i & (Cc - 1);
    g_hup[i] = fmaxf(0.f, fmaf(g_amax[i], g_scale[Cc + c], g_shift[Cc + c]));
}

// ---------------- final: BN+relu+concat+transpose to out [g, 256, l] ----------------
__global__ void final_kernel(float* __restrict__ out) {
    __shared__ float t[32][33];
    int g = blockIdx.z, c0 = blockIdx.y * 32, l0 = blockIdx.x * 32;
    int tx = threadIdx.x, ty = threadIdx.y;
    #pragma unroll
    for (int i = 0; i < 32; i += 8) {
        int l = l0 + ty + i;
        int c = c0 + tx;
        float v;
        if (c < Cc) v = g_a[((size_t)g * Ll + l) * Cc + c];
        else        v = g_amax[((size_t)(g / Nn) * Ll + l) * Cc + (c - Cc)];
        v = fmaxf(0.f, fmaf(v, g_scale[c], g_shift[c]));
        t[ty + i][tx] = v;                 // t[l'][c']
    }
    __syncthreads();
    #pragma unroll
    for (int i = 0; i < 32; i += 8) {
        int c = c0 + ty + i;
        int l = l0 + tx;
        out[((size_t)g * C2 + c) * Ll + l] = t[tx][ty + i];
    }
}

// ---------------- launch ----------------
extern "C" void kernel_launch(void* const* d_in, const int* in_sizes, int n_in,
                              void* d_out, int out_size) {
    const float* x  = (const float*)d_in[0];
    const void*  ei = d_in[1];   // int32 or int64, detected on device
    const float *W1 = (const float*)d_in[2],  *b1  = (const float*)d_in[3];
    const float *W2 = (const float*)d_in[4],  *b2  = (const float*)d_in[5];
    const float *W3 = (const float*)d_in[6],  *b3  = (const float*)d_in[7];
    const float *ga1 = (const float*)d_in[8],  *be1 = (const float*)d_in[9];
    const float *ga2 = (const float*)d_in[10], *be2 = (const float*)d_in[11];
    const float *ga3 = (const float*)d_in[12], *be3 = (const float*)d_in[13];
    float* out = (float*)d_out;

    // graph structure (rebuilt every call; deterministic)
    detect_dtype<<<1, 256>>>((const unsigned int*)ei);
    zero_counts<<<(Ll + 255) / 256, 256>>>();
    count_edges<<<Ee / 256, 256>>>(ei);
    scan_build<<<1, 256>>>();
    fill_edges<<<Ee / 256, 256>>>(ei);

    transpose_x<<<dim3(Ll / 32, C0 / 32, Gg), dim3(32, 8)>>>(x);

    const int rowsGL = Gg * Ll;   // 131072
    const int rowsBL = Bb * Ll;   // 8192

    // ---- layer 1:  a = (A h0) W1 + b1 ----
    agg1_kernel<<<rowsGL / (128 / (C0 / 4)), 128>>>();          // 16384 blocks
    gemm1_kernel<<<rowsGL / 32, 128>>>(W1, b1);
    amax_kernel<<<rowsBL, 128>>>();
    zero_stats<<<1, C2>>>();
    stats_a_kernel<<<256, 128>>>();
    stats_amax_kernel<<<32, 128>>>();
    bn_kernel<<<1, C2>>>(ga1, be1);
    act_low_kernel<<<rowsGL * Cc / 256, 256>>>();
    act_up_kernel<<<rowsBL * Cc / 256, 256>>>();

    // ---- layer 2:  hW = hlow@W2low + (hup@W2up)[b];  a = A hW + b2 ----
    gemmU_kernel<<<rowsBL / 32, 128>>>(W2 + Cc * Cc);
    gemmM_kernel<<<rowsGL / 32, 128>>>(W2);
    agg2_kernel<<<rowsGL / 4, 128>>>(b2);
    amax_kernel<<<rowsBL, 128>>>();
    zero_stats<<<1, C2>>>();
    stats_a_kernel<<<256, 128>>>();
    stats_amax_kernel<<<32, 128>>>();
    bn_kernel<<<1, C2>>>(ga2, be2);
    act_low_kernel<<<rowsGL * Cc / 256, 256>>>();
    act_up_kernel<<<rowsBL * Cc / 256, 256>>>();

    // ---- layer 3 ----
    gemmU_kernel<<<rowsBL / 32, 128>>>(W3 + Cc * Cc);
    gemmM_kernel<<<rowsGL / 32, 128>>>(W3);
    agg2_kernel<<<rowsGL / 4, 128>>>(b3);
    amax_kernel<<<rowsBL, 128>>>();
    zero_stats<<<1, C2>>>();
    stats_a_kernel<<<256, 128>>>();
    stats_amax_kernel<<<32, 128>>>();
    bn_kernel<<<1, C2>>>(ga3, be3);

    // fused BN + relu + concat + transpose into output layout [b*n, 256, l]
    final_kernel<<<dim3(Ll / 32, C2 / 32, Gg), dim3(32, 8)>>>(out);
}

// round 8
// speedup vs baseline: 1.1089x; 1.1089x over previous
#include <cuda_runtime.h>
#include <math.h>

// Problem constants
#define Bb 4
#define Nn 16
#define Gg 64            // Bb*Nn
#define Ll 2048
#define Ee 32768
#define C0 64
#define Cc 128
#define C2 256
#define EPSf 1e-5

typedef unsigned long long ull;

// packed f32x2 FMA: d = a*b + d (elementwise on 2 packed floats)
#define FFMA2(d, a, b) asm("fma.rn.f32x2 %0, %1, %2, %3;" : "=l"(d) : "l"(a), "l"(b), "l"(d))

// ---------------- scratch (static device globals; no allocation) ----------------
__device__ float g_h0  [Gg*Ll*C0];   // transposed x        [g,l,64]
__device__ float g_agg0[Gg*Ll*C0];   // A @ h0              [g,l,64]
__device__ float g_hW  [Gg*Ll*Cc];   // GEMM out pre-agg    [g,l,128]
__device__ float g_a   [Gg*Ll*Cc];   // post-agg (+bias)    [g,l,128]
__device__ float g_U   [Bb*Ll*Cc];   // act(amax) @ W_up    [b,l,128]
__device__ float g_amax[Bb*Ll*Cc];   // max over n of a     [b,l,128]

__device__ ull g_Wp1[(C0/2)*Cc];     // packed W1  (32 kpairs x 128)
__device__ ull g_Wp2[(C2/2)*Cc];     // packed W2  (128 kpairs x 128; [0:64)=low, [64:128)=up)
__device__ ull g_Wp3[(C2/2)*Cc];     // packed W3

__device__ double g_sum[C2], g_sumsq[C2];
__device__ float  g_scale[C2], g_shift[C2];

__device__ int   g_cnt[Ll], g_cnt2[Ll];
__device__ int   g_rowptr[Ll+1];
__device__ int   g_col[Ee];
__device__ float g_enorm[Ee];
__device__ float g_dinv[Ll], g_selfnorm[Ll];
__device__ int   g_is64;   // 1 if edge_index buffer holds int64, 0 if int32

// ---------------- edge dtype detection + safe accessor ----------------
__global__ void detect_dtype(const unsigned int* __restrict__ w) {
    __shared__ int any;
    if (threadIdx.x == 0) any = 0;
    __syncthreads();
    for (int i = 2 * threadIdx.x + 1; i < 16384; i += 2 * blockDim.x)
        if (w[i] != 0u) any = 1;
    __syncthreads();
    if (threadIdx.x == 0) g_is64 = (any == 0) ? 1 : 0;
}

__device__ __forceinline__ int edge_at(const void* __restrict__ ei, int idx) {
    int v;
    if (g_is64) v = (int)(((const long long*)ei)[idx]);
    else        v = ((const int*)ei)[idx];
    return v & (Ll - 1);   // defensive mask; no-op for valid data
}

// ---------------- graph structure build ----------------
__global__ void zero_counts() {
    int i = blockIdx.x * blockDim.x + threadIdx.x;
    if (i < Ll) { g_cnt[i] = 0; g_cnt2[i] = 0; }
}

__global__ void count_edges(const void* __restrict__ ei) {
    int e = blockIdx.x * blockDim.x + threadIdx.x;
    if (e < Ee) atomicAdd(&g_cnt[edge_at(ei, Ee + e)], 1);
}

// one block, 256 threads: shuffle-based exclusive scan -> g_rowptr, dinv/selfnorm
__global__ void scan_build() {
    const int CH = Ll / 256;  // 8
    int tid = threadIdx.x, lane = tid & 31, wid = tid >> 5;
    int base = tid * CH;
    int vals[CH];
    int s = 0;
    #pragma unroll
    for (int i = 0; i < CH; i++) { vals[i] = g_cnt[base + i]; s += vals[i]; }
    int own = s;
    #pragma unroll
    for (int off = 1; off < 32; off <<= 1) {
        int t = __shfl_up_sync(0xffffffffu, s, off);
        if (lane >= off) s += t;
    }
    __shared__ int wsum[8], woff[8];
    if (lane == 31) wsum[wid] = s;
    __syncthreads();
    if (tid == 0) { int r = 0; for (int w = 0; w < 8; w++) { woff[w] = r; r += wsum[w]; } }
    __syncthreads();
    int run = woff[wid] + s - own;   // exclusive prefix
    #pragma unroll
    for (int i = 0; i < CH; i++) {
        g_rowptr[base + i] = run; run += vals[i];
        float deg = (float)vals[i] + 2.0f;          // self loop weight 2
        g_dinv[base + i] = rsqrtf(deg);
        g_selfnorm[base + i] = 2.0f / deg;
    }
    if (tid == 255) g_rowptr[Ll] = run;
}

__global__ void fill_edges(const void* __restrict__ ei) {
    int e = blockIdx.x * blockDim.x + threadIdx.x;
    if (e < Ee) {
        int s = edge_at(ei, e);
        int d = edge_at(ei, Ee + e);
        int pos = g_rowptr[d] + atomicAdd(&g_cnt2[d], 1);
        g_col[pos] = s;
        g_enorm[pos] = g_dinv[s] * g_dinv[d];
    }
}

// ---------------- pack weights into u64 k-pairs ----------------
__global__ void pack_weights(const float* __restrict__ W1,
                             const float* __restrict__ W2,
                             const float* __restrict__ W3) {
    int flat = blockIdx.x * blockDim.x + threadIdx.x;   // 0 .. 288*128-1
    const int N1 = (C0/2) * Cc;          // 4096
    const int N2 = (C2/2) * Cc;          // 16384
    if (flat < N1) {
        int kp = flat / Cc, c = flat % Cc;
        unsigned lo = __float_as_uint(W1[(2*kp)   * Cc + c]);
        unsigned hi = __float_as_uint(W1[(2*kp+1) * Cc + c]);
        g_Wp1[flat] = (ull)lo | ((ull)hi << 32);
    } else if (flat < N1 + N2) {
        int f = flat - N1;
        int kp = f / Cc, c = f % Cc;
        unsigned lo = __float_as_uint(W2[(2*kp)   * Cc + c]);
        unsigned hi = __float_as_uint(W2[(2*kp+1) * Cc + c]);
        g_Wp2[f] = (ull)lo | ((ull)hi << 32);
    } else if (flat < N1 + 2*N2) {
        int f = flat - N1 - N2;
        int kp = f / Cc, c = f % Cc;
        unsigned lo = __float_as_uint(W3[(2*kp)   * Cc + c]);
        unsigned hi = __float_as_uint(W3[(2*kp+1) * Cc + c]);
        g_Wp3[f] = (ull)lo | ((ull)hi << 32);
    }
}

// ---------------- transpose x [b,n,c,l] -> g_h0 [g,l,c] ----------------
__global__ void transpose_x(const float* __restrict__ x) {
    __shared__ float t[32][33];
    int g = blockIdx.z, c0 = blockIdx.y * 32, l0 = blockIdx.x * 32;
    int tx = threadIdx.x, ty = threadIdx.y;
    #pragma unroll
    for (int i = 0; i < 32; i += 8) {
        int c = c0 + ty + i, l = l0 + tx;
        t[ty + i][tx] = x[((size_t)(g * C0 + c)) * Ll + l];
    }
    __syncthreads();
    #pragma unroll
    for (int i = 0; i < 32; i += 8) {
        int l = l0 + ty + i, c = c0 + tx;
        g_h0[((size_t)g * Ll + l) * C0 + c] = t[tx][ty + i];
    }
}

// ---------------- GEMM: Y[row, 0..127] = act(X[row, 0..K-1]) @ W[K,128] (+U)(+bias) ----------------
// FFMA2 packed f32x2, k-pair packing (even/odd partial sums recombined at the end).
// ACT: applies y = relu(x*scale[c] + shift[c]) to the input while staging into smem.
template <int K, bool ADD_U, bool ADD_BIAS, bool ACT>
__device__ __forceinline__ void gemm_body(
    const float* __restrict__ X, const ull* __restrict__ Wp,
    const float* __restrict__ bias, const float* __restrict__ U,
    const float* __restrict__ scale, const float* __restrict__ shift,
    float* __restrict__ Y)
{
    __shared__ __align__(16) float sX[32 * K];
    __shared__ float s_sc[K], s_sh[K];
    int tid = threadIdx.x;
    size_t row0 = (size_t)blockIdx.x * 32;

    if (ACT) {
        if (tid < K) { s_sc[tid] = scale[tid]; s_sh[tid] = shift[tid]; }
        __syncthreads();
    }

    const float4* Xv = (const float4*)(X + row0 * K);
    float4* sv = (float4*)sX;
    #pragma unroll
    for (int i = tid; i < 32 * K / 4; i += 128) {
        float4 v = Xv[i];
        if (ACT) {
            int c = (i * 4) % K;
            v.x = fmaxf(0.f, fmaf(v.x, s_sc[c + 0], s_sh[c + 0]));
            v.y = fmaxf(0.f, fmaf(v.y, s_sc[c + 1], s_sh[c + 1]));
            v.z = fmaxf(0.f, fmaf(v.z, s_sc[c + 2], s_sh[c + 2]));
            v.w = fmaxf(0.f, fmaf(v.w, s_sc[c + 3], s_sh[c + 3]));
        }
        sv[i] = v;
    }
    __syncthreads();

    ull acc[32];
    #pragma unroll
    for (int r = 0; r < 32; r++) acc[r] = 0ull;   // bit pattern {0.f, 0.f}

    for (int kq = 0; kq < K / 4; kq++) {          // 4 k-values (= 2 k-pairs) per iter
        ull wp0 = Wp[(2 * kq)     * Cc + tid];
        ull wp1 = Wp[(2 * kq + 1) * Cc + tid];
        #pragma unroll
        for (int r = 0; r < 32; r++) {
            ulonglong2 xv = *(const ulonglong2*)(sX + r * K + 4 * kq);
            FFMA2(acc[r], xv.x, wp0);
            FFMA2(acc[r], xv.y, wp1);
        }
    }

    float bv = ADD_BIAS ? bias[tid] : 0.f;
    #pragma unroll
    for (int r = 0; r < 32; r++) {
        size_t row = row0 + r;
        float lo = __uint_as_float((unsigned)acc[r]);
        float hi = __uint_as_float((unsigned)(acc[r] >> 32));
        float v = lo + hi + bv;
        if (ADD_U) {
            size_t l = row % Ll;
            size_t b = row / ((size_t)Nn * Ll);
            v += U[(b * Ll + l) * Cc + tid];
        }
        Y[row * Cc + tid] = v;
    }
}

__global__ __launch_bounds__(128) void gemm1_kernel(const float* __restrict__ bias) {
    gemm_body<C0, false, true, false>(g_agg0, g_Wp1, bias, nullptr, nullptr, nullptr, g_a);
}
// U = relu(bn(amax)) @ W_up      (upper-half BN params: offset Cc)
__global__ __launch_bounds__(128) void gemmU_kernel(int wsel) {
    const ull* wp = ((wsel == 2) ? g_Wp2 : g_Wp3) + (Cc / 2) * Cc;   // kpairs 64..127 = rows 128..255
    gemm_body<Cc, false, false, true>(g_amax, wp, nullptr, nullptr, g_scale + Cc, g_shift + Cc, g_U);
}
// hW = relu(bn(a)) @ W_low + U[b]  (lower-half BN params)
__global__ __launch_bounds__(128) void gemmM_kernel(int wsel) {
    const ull* wp = (wsel == 2) ? g_Wp2 : g_Wp3;
    gemm_body<Cc, true, false, true>(g_a, wp, nullptr, g_U, g_scale, g_shift, g_hW);
}

// ---------------- aggregation ----------------
template <int C, bool ADD_BIAS>
__device__ __forceinline__ void agg_body(
    const float* __restrict__ Xin, const float* __restrict__ bias, float* __restrict__ Yout)
{
    constexpr int TPN = C / 4;
    constexpr int NPB = 128 / TPN;
    int lane = threadIdx.x % TPN;
    int nidx = threadIdx.x / TPN;
    size_t ng = (size_t)blockIdx.x * NPB + nidx;     // over G*L
    int node = (int)(ng % Ll);
    size_t g = ng / Ll;
    const float4* Xg = (const float4*)(Xin + g * Ll * C);

    float sn = g_selfnorm[node];
    float4 xv = Xg[(size_t)node * TPN + lane];
    float4 acc = make_float4(sn * xv.x, sn * xv.y, sn * xv.z, sn * xv.w);

    int s = g_rowptr[node], e = g_rowptr[node + 1];
    for (int i = s; i < e; i++) {
        float nw = g_enorm[i];
        float4 v = Xg[(size_t)g_col[i] * TPN + lane];
        acc.x += nw * v.x; acc.y += nw * v.y; acc.z += nw * v.z; acc.w += nw * v.w;
    }
    if (ADD_BIAS) {
        float4 bv = ((const float4*)bias)[lane];
        acc.x += bv.x; acc.y += bv.y; acc.z += bv.z; acc.w += bv.w;
    }
    ((float4*)Yout)[ng * TPN + lane] = acc;
}

__global__ __launch_bounds__(128) void agg1_kernel() {
    agg_body<C0, false>(g_h0, nullptr, g_agg0);
}
__global__ __launch_bounds__(128) void agg2_kernel(const float* __restrict__ bias) {
    agg_body<Cc, true>(g_hW, bias, g_a);
}

// ---------------- amax over n (also zeroes BN accumulators) ----------------
__global__ void amax_kernel() {
    int tid = threadIdx.x;                 // channel
    if (blockIdx.x == 0) {                 // zero stats accumulators for this layer
        g_sum[tid] = 0.0;        g_sumsq[tid] = 0.0;
        g_sum[Cc + tid] = 0.0;   g_sumsq[Cc + tid] = 0.0;
    }
    size_t bl = blockIdx.x;                // over B*L
    size_t b = bl / Ll, l = bl % Ll;
    float m = -3.4e38f;
    #pragma unroll
    for (int n = 0; n < Nn; n++)
        m = fmaxf(m, g_a[(((b * Nn + n) * Ll) + l) * Cc + tid]);
    g_amax[bl * Cc + tid] = m;
}

// ---------------- BN stats (merged a-part + amax-part) ----------------
__global__ void stats_all_kernel() {
    int c = threadIdx.x;                       // 128
    if (blockIdx.x < 256) {
        const size_t rows = (size_t)Gg * Ll;   // 131072
        size_t per = rows / 256;
        size_t r0 = (size_t)blockIdx.x * per;
        float s = 0.f, ss = 0.f;
        for (size_t r = r0; r < r0 + per; r++) {
            float v = g_a[r * Cc + c];
            s += v; ss += v * v;
        }
        atomicAdd(&g_sum[c], (double)s);
        atomicAdd(&g_sumsq[c], (double)ss);
    } else {
        int blk = blockIdx.x - 256;            // 0..31
        const size_t rows = (size_t)Bb * Ll;   // 8192
        size_t per = rows / 32;
        size_t r0 = (size_t)blk * per;
        float s = 0.f, ss = 0.f;
        for (size_t r = r0; r < r0 + per; r++) {
            float v = g_amax[r * Cc + c];
            s += v; ss += v * v;
        }
        atomicAdd(&g_sum[Cc + c], (double)s);
        atomicAdd(&g_sumsq[Cc + c], (double)ss);
    }
}

__global__ void bn_kernel(const float* __restrict__ gamma, const float* __restrict__ beta) {
    int c = threadIdx.x;                       // 256
    double cnt = (c < Cc) ? (double)((size_t)Gg * Ll) : (double)((size_t)Bb * Ll);
    double mean = g_sum[c] / cnt;
    double var  = g_sumsq[c] / cnt - mean * mean;
    double inv  = 1.0 / sqrt(var + (double)EPSf);
    double sc   = (double)gamma[c] * inv;
    g_scale[c] = (float)sc;
    g_shift[c] = (float)((double)beta[c] - mean * sc);
}

// ---------------- final: BN+relu+concat+transpose to out [g, 256, l] ----------------
__global__ void final_kernel(float* __restrict__ out) {
    __shared__ float t[32][33];
    int g = blockIdx.z, c0 = blockIdx.y * 32, l0 = blockIdx.x * 32;
    int tx = threadIdx.x, ty = threadIdx.y;
    #pragma unroll
    for (int i = 0; i < 32; i += 8) {
        int l = l0 + ty + i;
        int c = c0 + tx;
        float v;
        if (c < Cc) v = g_a[((size_t)g * Ll + l) * Cc + c];
        else        v = g_amax[((size_t)(g / Nn) * Ll + l) * Cc + (c - Cc)];
        v = fmaxf(0.f, fmaf(v, g_scale[c], g_shift[c]));
        t[ty + i][tx] = v;
    }
    __syncthreads();
    #pragma unroll
    for (int i = 0; i < 32; i += 8) {
        int c = c0 + ty + i;
        int l = l0 + tx;
        out[((size_t)g * C2 + c) * Ll + l] = t[tx][ty + i];
    }
}

// ---------------- launch ----------------
extern "C" void kernel_launch(void* const* d_in, const int* in_sizes, int n_in,
                              void* d_out, int out_size) {
    const float* x  = (const float*)d_in[0];
    const void*  ei = d_in[1];   // int32 or int64, detected on device
    const float *W1 = (const float*)d_in[2],  *b1  = (const float*)d_in[3];
    const float *W2 = (const float*)d_in[4],  *b2  = (const float*)d_in[5];
    const float *W3 = (const float*)d_in[6],  *b3  = (const float*)d_in[7];
    const float *ga1 = (const float*)d_in[8],  *be1 = (const float*)d_in[9];
    const float *ga2 = (const float*)d_in[10], *be2 = (const float*)d_in[11];
    const float *ga3 = (const float*)d_in[12], *be3 = (const float*)d_in[13];
    float* out = (float*)d_out;

    // graph structure + weight packing (rebuilt every call; deterministic)
    detect_dtype<<<1, 256>>>((const unsigned int*)ei);
    zero_counts<<<(Ll + 255) / 256, 256>>>();
    count_edges<<<Ee / 256, 256>>>(ei);
    scan_build<<<1, 256>>>();
    fill_edges<<<Ee / 256, 256>>>(ei);
    pack_weights<<<(288 * 128 + 255) / 256, 256>>>(W1, W2, W3);

    transpose_x<<<dim3(Ll / 32, C0 / 32, Gg), dim3(32, 8)>>>(x);

    const int rowsGL = Gg * Ll;   // 131072
    const int rowsBL = Bb * Ll;   // 8192

    // ---- layer 1:  a = (A h0) W1 + b1 ----
    agg1_kernel<<<rowsGL / 8, 128>>>();
    gemm1_kernel<<<rowsGL / 32, 128>>>(b1);
    amax_kernel<<<rowsBL, 128>>>();
    stats_all_kernel<<<288, 128>>>();
    bn_kernel<<<1, C2>>>(ga1, be1);

    // ---- layer 2:  hW = act(a)@W2low + (act(amax)@W2up)[b];  a = A hW + b2 ----
    gemmU_kernel<<<rowsBL / 32, 128>>>(2);
    gemmM_kernel<<<rowsGL / 32, 128>>>(2);
    agg2_kernel<<<rowsGL / 4, 128>>>(b2);
    amax_kernel<<<rowsBL, 128>>>();
    stats_all_kernel<<<288, 128>>>();
    bn_kernel<<<1, C2>>>(ga2, be2);

    // ---- layer 3 ----
    gemmU_kernel<<<rowsBL / 32, 128>>>(3);
    gemmM_kernel<<<rowsGL / 32, 128>>>(3);
    agg2_kernel<<<rowsGL / 4, 128>>>(b3);
    amax_kernel<<<rowsBL, 128>>>();
    stats_all_kernel<<<288, 128>>>();
    bn_kernel<<<1, C2>>>(ga3, be3);

    // fused BN + relu + concat + transpose into output layout [b*n, 256, l]
    final_kernel<<<dim3(Ll / 32, C2 / 32, Gg), dim3(32, 8)>>>(out);
}

// round 9
// speedup vs baseline: 1.1188x; 1.0089x over previous
#include <cuda_runtime.h>
#include <math.h>

// Problem constants
#define Bb 4
#define Nn 16
#define Gg 64            // Bb*Nn
#define Ll 2048
#define Ee 32768
#define C0 64
#define Cc 128
#define C2 256
#define EPSf 1e-5

typedef unsigned long long ull;

// packed f32x2 FMA: d = a*b + d (elementwise on 2 packed floats)
#define FFMA2(d, a, b) asm("fma.rn.f32x2 %0, %1, %2, %3;" : "=l"(d) : "l"(a), "l"(b), "l"(d))

// ---------------- scratch (static device globals; no allocation) ----------------
__device__ float g_h0  [Gg*Ll*C0];   // transposed x        [g,l,64]
__device__ float g_agg0[Gg*Ll*C0];   // A @ h0              [g,l,64]
__device__ float g_hW  [Gg*Ll*Cc];   // GEMM out pre-agg    [g,l,128]
__device__ float g_a   [Gg*Ll*Cc];   // post-agg (+bias)    [g,l,128]
__device__ float g_U   [Bb*Ll*Cc];   // act(amax) @ W_up    [b,l,128]
__device__ float g_amax[Bb*Ll*Cc];   // max over n of a     [b,l,128]

__device__ ull g_Wp1[(C0/2)*Cc];     // packed W1  (32 kpairs x 128)
__device__ ull g_Wp2[(C2/2)*Cc];     // packed W2  (128 kpairs x 128; [0:64)=low, [64:128)=up)
__device__ ull g_Wp3[(C2/2)*Cc];     // packed W3

__device__ double g_sum[C2], g_sumsq[C2];
__device__ float  g_scale[C2], g_shift[C2];

__device__ int   g_cnt[Ll], g_cnt2[Ll];
__device__ int   g_rowptr[Ll+1];
__device__ int   g_col[Ee];
__device__ float g_enorm[Ee];
__device__ float g_dinv[Ll], g_selfnorm[Ll];
__device__ int   g_is64;   // 1 if edge_index buffer holds int64, 0 if int32

// ---------------- edge dtype detection + safe accessor ----------------
__global__ void detect_dtype(const unsigned int* __restrict__ w) {
    __shared__ int any;
    if (threadIdx.x == 0) any = 0;
    __syncthreads();
    for (int i = 2 * threadIdx.x + 1; i < 16384; i += 2 * blockDim.x)
        if (w[i] != 0u) any = 1;
    __syncthreads();
    if (threadIdx.x == 0) g_is64 = (any == 0) ? 1 : 0;
}

__device__ __forceinline__ int edge_at(const void* __restrict__ ei, int idx) {
    int v;
    if (g_is64) v = (int)(((const long long*)ei)[idx]);
    else        v = ((const int*)ei)[idx];
    return v & (Ll - 1);   // defensive mask; no-op for valid data
}

// ---------------- graph structure build ----------------
__global__ void zero_counts() {
    int i = blockIdx.x * blockDim.x + threadIdx.x;
    if (i < Ll) { g_cnt[i] = 0; g_cnt2[i] = 0; }
}

__global__ void count_edges(const void* __restrict__ ei) {
    int e = blockIdx.x * blockDim.x + threadIdx.x;
    if (e < Ee) atomicAdd(&g_cnt[edge_at(ei, Ee + e)], 1);
}

// one block, 256 threads: shuffle-based exclusive scan -> g_rowptr, dinv/selfnorm
__global__ void scan_build() {
    const int CH = Ll / 256;  // 8
    int tid = threadIdx.x, lane = tid & 31, wid = tid >> 5;
    int base = tid * CH;
    int vals[CH];
    int s = 0;
    #pragma unroll
    for (int i = 0; i < CH; i++) { vals[i] = g_cnt[base + i]; s += vals[i]; }
    int own = s;
    #pragma unroll
    for (int off = 1; off < 32; off <<= 1) {
        int t = __shfl_up_sync(0xffffffffu, s, off);
        if (lane >= off) s += t;
    }
    __shared__ int wsum[8], woff[8];
    if (lane == 31) wsum[wid] = s;
    __syncthreads();
    if (tid == 0) { int r = 0; for (int w = 0; w < 8; w++) { woff[w] = r; r += wsum[w]; } }
    __syncthreads();
    int run = woff[wid] + s - own;   // exclusive prefix
    #pragma unroll
    for (int i = 0; i < CH; i++) {
        g_rowptr[base + i] = run; run += vals[i];
        float deg = (float)vals[i] + 2.0f;          // self loop weight 2
        g_dinv[base + i] = rsqrtf(deg);
        g_selfnorm[base + i] = 2.0f / deg;
    }
    if (tid == 255) g_rowptr[Ll] = run;
}

__global__ void fill_edges(const void* __restrict__ ei) {
    int e = blockIdx.x * blockDim.x + threadIdx.x;
    if (e < Ee) {
        int s = edge_at(ei, e);
        int d = edge_at(ei, Ee + e);
        int pos = g_rowptr[d] + atomicAdd(&g_cnt2[d], 1);
        g_col[pos] = s;
        g_enorm[pos] = g_dinv[s] * g_dinv[d];
    }
}

// ---------------- pack weights into u64 k-pairs ----------------
__global__ void pack_weights(const float* __restrict__ W1,
                             const float* __restrict__ W2,
                             const float* __restrict__ W3) {
    int flat = blockIdx.x * blockDim.x + threadIdx.x;   // 0 .. 288*128-1
    const int N1 = (C0/2) * Cc;          // 4096
    const int N2 = (C2/2) * Cc;          // 16384
    if (flat < N1) {
        int kp = flat / Cc, c = flat % Cc;
        unsigned lo = __float_as_uint(W1[(2*kp)   * Cc + c]);
        unsigned hi = __float_as_uint(W1[(2*kp+1) * Cc + c]);
        g_Wp1[flat] = (ull)lo | ((ull)hi << 32);
    } else if (flat < N1 + N2) {
        int f = flat - N1;
        int kp = f / Cc, c = f % Cc;
        unsigned lo = __float_as_uint(W2[(2*kp)   * Cc + c]);
        unsigned hi = __float_as_uint(W2[(2*kp+1) * Cc + c]);
        g_Wp2[f] = (ull)lo | ((ull)hi << 32);
    } else if (flat < N1 + 2*N2) {
        int f = flat - N1 - N2;
        int kp = f / Cc, c = f % Cc;
        unsigned lo = __float_as_uint(W3[(2*kp)   * Cc + c]);
        unsigned hi = __float_as_uint(W3[(2*kp+1) * Cc + c]);
        g_Wp3[f] = (ull)lo | ((ull)hi << 32);
    }
}

// ---------------- transpose x [b,n,c,l] -> g_h0 [g,l,c] ----------------
__global__ void transpose_x(const float* __restrict__ x) {
    __shared__ float t[32][33];
    int g = blockIdx.z, c0 = blockIdx.y * 32, l0 = blockIdx.x * 32;
    int tx = threadIdx.x, ty = threadIdx.y;
    #pragma unroll
    for (int i = 0; i < 32; i += 8) {
        int c = c0 + ty + i, l = l0 + tx;
        t[ty + i][tx] = x[((size_t)(g * C0 + c)) * Ll + l];
    }
    __syncthreads();
    #pragma unroll
    for (int i = 0; i < 32; i += 8) {
        int l = l0 + ty + i, c = c0 + tx;
        g_h0[((size_t)g * Ll + l) * C0 + c] = t[tx][ty + i];
    }
}

// ---------------- GEMM: Y[row, 0..127] = act(X[row, 0..K-1]) @ W[K,128] (+U)(+bias) ----------------
template <int K, bool ADD_U, bool ADD_BIAS, bool ACT>
__device__ __forceinline__ void gemm_body(
    const float* __restrict__ X, const ull* __restrict__ Wp,
    const float* __restrict__ bias, const float* __restrict__ U,
    const float* __restrict__ scale, const float* __restrict__ shift,
    float* __restrict__ Y)
{
    __shared__ __align__(16) float sX[32 * K];
    __shared__ float s_sc[K], s_sh[K];
    int tid = threadIdx.x;
    size_t row0 = (size_t)blockIdx.x * 32;

    if (ACT) {
        if (tid < K) { s_sc[tid] = scale[tid]; s_sh[tid] = shift[tid]; }
        __syncthreads();
    }

    const float4* Xv = (const float4*)(X + row0 * K);
    float4* sv = (float4*)sX;
    #pragma unroll
    for (int i = tid; i < 32 * K / 4; i += 128) {
        float4 v = Xv[i];
        if (ACT) {
            int c = (i * 4) % K;
            v.x = fmaxf(0.f, fmaf(v.x, s_sc[c + 0], s_sh[c + 0]));
            v.y = fmaxf(0.f, fmaf(v.y, s_sc[c + 1], s_sh[c + 1]));
            v.z = fmaxf(0.f, fmaf(v.z, s_sc[c + 2], s_sh[c + 2]));
            v.w = fmaxf(0.f, fmaf(v.w, s_sc[c + 3], s_sh[c + 3]));
        }
        sv[i] = v;
    }
    __syncthreads();

    ull acc[32];
    #pragma unroll
    for (int r = 0; r < 32; r++) acc[r] = 0ull;

    for (int kq = 0; kq < K / 4; kq++) {          // 4 k-values (= 2 k-pairs) per iter
        ull wp0 = Wp[(2 * kq)     * Cc + tid];
        ull wp1 = Wp[(2 * kq + 1) * Cc + tid];
        #pragma unroll
        for (int r = 0; r < 32; r++) {
            ulonglong2 xv = *(const ulonglong2*)(sX + r * K + 4 * kq);
            FFMA2(acc[r], xv.x, wp0);
            FFMA2(acc[r], xv.y, wp1);
        }
    }

    float bv = ADD_BIAS ? bias[tid] : 0.f;
    #pragma unroll
    for (int r = 0; r < 32; r++) {
        size_t row = row0 + r;
        float lo = __uint_as_float((unsigned)acc[r]);
        float hi = __uint_as_float((unsigned)(acc[r] >> 32));
        float v = lo + hi + bv;
        if (ADD_U) {
            size_t l = row % Ll;
            size_t b = row / ((size_t)Nn * Ll);
            v += U[(b * Ll + l) * Cc + tid];
        }
        Y[row * Cc + tid] = v;
    }
}

__global__ __launch_bounds__(128) void gemm1_kernel(const float* __restrict__ bias) {
    // block 0 zeroes the BN stat accumulators for this layer (consumed later by amax_stats)
    if (blockIdx.x == 0) {
        g_sum[threadIdx.x] = 0.0;       g_sumsq[threadIdx.x] = 0.0;
        g_sum[Cc + threadIdx.x] = 0.0;  g_sumsq[Cc + threadIdx.x] = 0.0;
    }
    gemm_body<C0, false, true, false>(g_agg0, g_Wp1, bias, nullptr, nullptr, nullptr, g_a);
}
// U = relu(bn(amax)) @ W_up      (upper-half BN params: offset Cc)
__global__ __launch_bounds__(128) void gemmU_kernel(int wsel) {
    const ull* wp = ((wsel == 2) ? g_Wp2 : g_Wp3) + (Cc / 2) * Cc;
    gemm_body<Cc, false, false, true>(g_amax, wp, nullptr, nullptr, g_scale + Cc, g_shift + Cc, g_U);
}
// hW = relu(bn(a)) @ W_low + U[b]  (lower-half BN params)
__global__ __launch_bounds__(128) void gemmM_kernel(int wsel) {
    const ull* wp = (wsel == 2) ? g_Wp2 : g_Wp3;
    gemm_body<Cc, true, false, true>(g_a, wp, nullptr, g_U, g_scale, g_shift, g_hW);
}

// ---------------- aggregation ----------------
template <int C, bool ADD_BIAS, bool ZERO_STATS>
__device__ __forceinline__ void agg_body(
    const float* __restrict__ Xin, const float* __restrict__ bias, float* __restrict__ Yout)
{
    if (ZERO_STATS && blockIdx.x == 0) {
        int t = threadIdx.x;
        g_sum[t] = 0.0;       g_sumsq[t] = 0.0;
        g_sum[Cc + t] = 0.0;  g_sumsq[Cc + t] = 0.0;
    }
    constexpr int TPN = C / 4;
    constexpr int NPB = 128 / TPN;
    int lane = threadIdx.x % TPN;
    int nidx = threadIdx.x / TPN;
    size_t ng = (size_t)blockIdx.x * NPB + nidx;     // over G*L
    int node = (int)(ng % Ll);
    size_t g = ng / Ll;
    const float4* Xg = (const float4*)(Xin + g * Ll * C);

    float sn = g_selfnorm[node];
    float4 xv = Xg[(size_t)node * TPN + lane];
    float4 acc = make_float4(sn * xv.x, sn * xv.y, sn * xv.z, sn * xv.w);

    int s = g_rowptr[node], e = g_rowptr[node + 1];
    for (int i = s; i < e; i++) {
        float nw = g_enorm[i];
        float4 v = Xg[(size_t)g_col[i] * TPN + lane];
        acc.x += nw * v.x; acc.y += nw * v.y; acc.z += nw * v.z; acc.w += nw * v.w;
    }
    if (ADD_BIAS) {
        float4 bv = ((const float4*)bias)[lane];
        acc.x += bv.x; acc.y += bv.y; acc.z += bv.z; acc.w += bv.w;
    }
    ((float4*)Yout)[ng * TPN + lane] = acc;
}

__global__ __launch_bounds__(128) void agg1_kernel() {
    agg_body<C0, false, false>(g_h0, nullptr, g_agg0);
}
__global__ __launch_bounds__(128) void agg2_kernel(const float* __restrict__ bias) {
    agg_body<Cc, true, true>(g_hW, bias, g_a);
}

// ---------------- fused amax + BN stats: ONE pass over g_a ----------------
// grid = 1024 blocks x 128 threads; each block handles 8 (b,l) positions.
// Thread owns channel c; reads the 16 n-values (needed for max anyway),
// accumulating sum/sumsq of a and of amax in registers; 4 atomics at the end.
__global__ void amax_stats_kernel() {
    int c = threadIdx.x;
    float s_a = 0.f, ss_a = 0.f, s_m = 0.f, ss_m = 0.f;
    size_t base = (size_t)blockIdx.x * 8;
    #pragma unroll 1
    for (int j = 0; j < 8; j++) {
        size_t bl = base + j;                 // over B*L = 8192
        size_t b = bl / Ll, l = bl % Ll;
        const float* p = g_a + ((b * Nn) * Ll + l) * Cc + c;
        float m = -3.4e38f;
        #pragma unroll
        for (int n = 0; n < Nn; n++) {
            float v = p[(size_t)n * Ll * Cc];
            s_a += v; ss_a += v * v;
            m = fmaxf(m, v);
        }
        g_amax[bl * Cc + c] = m;
        s_m += m; ss_m += m * m;
    }
    atomicAdd(&g_sum[c],        (double)s_a);
    atomicAdd(&g_sumsq[c],      (double)ss_a);
    atomicAdd(&g_sum[Cc + c],   (double)s_m);
    atomicAdd(&g_sumsq[Cc + c], (double)ss_m);
}

__global__ void bn_kernel(const float* __restrict__ gamma, const float* __restrict__ beta) {
    int c = threadIdx.x;                       // 256
    double cnt = (c < Cc) ? (double)((size_t)Gg * Ll) : (double)((size_t)Bb * Ll);
    double mean = g_sum[c] / cnt;
    double var  = g_sumsq[c] / cnt - mean * mean;
    double inv  = 1.0 / sqrt(var + (double)EPSf);
    double sc   = (double)gamma[c] * inv;
    g_scale[c] = (float)sc;
    g_shift[c] = (float)((double)beta[c] - mean * sc);
}

// ---------------- final: BN+relu+concat+transpose to out [g, 256, l] ----------------
__global__ void final_kernel(float* __restrict__ out) {
    __shared__ float t[32][33];
    int g = blockIdx.z, c0 = blockIdx.y * 32, l0 = blockIdx.x * 32;
    int tx = threadIdx.x, ty = threadIdx.y;
    #pragma unroll
    for (int i = 0; i < 32; i += 8) {
        int l = l0 + ty + i;
        int c = c0 + tx;
        float v;
        if (c < Cc) v = g_a[((size_t)g * Ll + l) * Cc + c];
        else        v = g_amax[((size_t)(g / Nn) * Ll + l) * Cc + (c - Cc)];
        v = fmaxf(0.f, fmaf(v, g_scale[c], g_shift[c]));
        t[ty + i][tx] = v;
    }
    __syncthreads();
    #pragma unroll
    for (int i = 0; i < 32; i += 8) {
        int c = c0 + ty + i;
        int l = l0 + tx;
        out[((size_t)g * C2 + c) * Ll + l] = t[tx][ty + i];
    }
}

// ---------------- launch ----------------
extern "C" void kernel_launch(void* const* d_in, const int* in_sizes, int n_in,
                              void* d_out, int out_size) {
    const float* x  = (const float*)d_in[0];
    const void*  ei = d_in[1];   // int32 or int64, detected on device
    const float *W1 = (const float*)d_in[2],  *b1  = (const float*)d_in[3];
    const float *W2 = (const float*)d_in[4],  *b2  = (const float*)d_in[5];
    const float *W3 = (const float*)d_in[6],  *b3  = (const float*)d_in[7];
    const float *ga1 = (const float*)d_in[8],  *be1 = (const float*)d_in[9];
    const float *ga2 = (const float*)d_in[10], *be2 = (const float*)d_in[11];
    const float *ga3 = (const float*)d_in[12], *be3 = (const float*)d_in[13];
    float* out = (float*)d_out;

    // graph structure + weight packing (rebuilt every call; deterministic)
    detect_dtype<<<1, 256>>>((const unsigned int*)ei);
    zero_counts<<<(Ll + 255) / 256, 256>>>();
    count_edges<<<Ee / 256, 256>>>(ei);
    scan_build<<<1, 256>>>();
    fill_edges<<<Ee / 256, 256>>>(ei);
    pack_weights<<<(288 * 128 + 255) / 256, 256>>>(W1, W2, W3);

    transpose_x<<<dim3(Ll / 32, C0 / 32, Gg), dim3(32, 8)>>>(x);

    const int rowsGL = Gg * Ll;   // 131072
    const int rowsBL = Bb * Ll;   // 8192

    // ---- layer 1:  a = (A h0) W1 + b1 ----
    agg1_kernel<<<rowsGL / 8, 128>>>();
    gemm1_kernel<<<rowsGL / 32, 128>>>(b1);       // also zeroes BN accumulators
    amax_stats_kernel<<<rowsBL / 8, 128>>>();
    bn_kernel<<<1, C2>>>(ga1, be1);

    // ---- layer 2:  hW = act(a)@W2low + (act(amax)@W2up)[b];  a = A hW + b2 ----
    gemmU_kernel<<<rowsBL / 32, 128>>>(2);
    gemmM_kernel<<<rowsGL / 32, 128>>>(2);
    agg2_kernel<<<rowsGL / 4, 128>>>(b2);         // also zeroes BN accumulators
    amax_stats_kernel<<<rowsBL / 8, 128>>>();
    bn_kernel<<<1, C2>>>(ga2, be2);

    // ---- layer 3 ----
    gemmU_kernel<<<rowsBL / 32, 128>>>(3);
    gemmM_kernel<<<rowsGL / 32, 128>>>(3);
    agg2_kernel<<<rowsGL / 4, 128>>>(b3);
    amax_stats_kernel<<<rowsBL / 8, 128>>>();
    bn_kernel<<<1, C2>>>(ga3, be3);

    // fused BN + relu + concat + transpose into output layout [b*n, 256, l]
    final_kernel<<<dim3(Ll / 32, C2 / 32, Gg), dim3(32, 8)>>>(out);
}

// round 10
// speedup vs baseline: 1.3485x; 1.2053x over previous
#include <cuda_runtime.h>
#include <cuda_fp16.h>
#include <math.h>

// Problem constants
#define Bb 4
#define Nn 16
#define Gg 64            // Bb*Nn
#define Ll 2048
#define Ee 32768
#define C0 64
#define Cc 128
#define C2 256
#define EPSf 1e-5

typedef unsigned long long ull;

// packed f32x2 FMA: d = a*b + d (elementwise on 2 packed floats)
#define FFMA2(d, a, b) asm("fma.rn.f32x2 %0, %1, %2, %3;" : "=l"(d) : "l"(a), "l"(b), "l"(d))

// ---------------- scratch (static device globals; no allocation) ----------------
__device__ float  g_h0  [Gg*Ll*C0];   // transposed x        [g,l,64]
__device__ float  g_agg0[Gg*Ll*C0];   // A @ h0              [g,l,64]
__device__ __half g_hWh [Gg*Ll*Cc];   // GEMM out pre-agg    [g,l,128] fp16
__device__ float  g_a   [Gg*Ll*Cc];   // post-agg (+bias)    [g,l,128]
__device__ float  g_U   [Bb*Ll*Cc];   // act(amax) @ W_up    [b,l,128]
__device__ float  g_amax[Bb*Ll*Cc];   // max over n of a     [b,l,128]

__device__ ull g_Wp1[(C0/2)*Cc];     // packed W1  (32 kpairs x 128)
__device__ ull g_Wp2[(C2/2)*Cc];     // packed W2  (128 kpairs x 128; [0:64)=low, [64:128)=up)
__device__ ull g_Wp3[(C2/2)*Cc];     // packed W3

__device__ double g_sum[C2], g_sumsq[C2];
__device__ float  g_scale[C2], g_shift[C2];

__device__ int   g_rowptr[Ll+1];
__device__ int   g_col[Ee];
__device__ float g_enorm[Ee];
__device__ float g_selfnorm[Ll];

// ---------------- fused graph build: detect dtype + count + scan + fill ----------------
// ONE block, 1024 threads. All counting/scan state in shared memory.
__global__ __launch_bounds__(1024) void graph_build(const unsigned int* __restrict__ w) {
    __shared__ int   s_any;
    __shared__ int   s_cnt[Ll];
    __shared__ int   s_base[Ll];
    __shared__ float s_dinv[Ll];
    __shared__ int   s_wsum[32];
    int tid = threadIdx.x;

    if (tid == 0) s_any = 0;
    s_cnt[tid] = 0; s_cnt[tid + 1024] = 0;
    __syncthreads();

    // dtype detect: int64 layout with values<2048 -> all odd u32 words zero
    int any = 0;
    for (int i = 2 * tid + 1; i < 16384; i += 2048)
        if (w[i] != 0u) any = 1;
    if (any) s_any = 1;
    __syncthreads();
    const int is64 = (s_any == 0);

    // count in-degree (smem atomics)
    for (int e = tid; e < Ee; e += 1024) {
        int d = (is64 ? (int)w[2 * (Ee + e)] : (int)w[Ee + e]) & (Ll - 1);
        atomicAdd(&s_cnt[d], 1);
    }
    __syncthreads();

    // exclusive scan over 2048 counts (2 per thread)
    int n0 = 2 * tid, n1 = 2 * tid + 1;
    int v0 = s_cnt[n0], v1 = s_cnt[n1];
    int s = v0 + v1;
    int lane = tid & 31, wid = tid >> 5;
    int own = s;
    #pragma unroll
    for (int off = 1; off < 32; off <<= 1) {
        int t = __shfl_up_sync(0xffffffffu, s, off);
        if (lane >= off) s += t;
    }
    if (lane == 31) s_wsum[wid] = s;
    __syncthreads();
    if (wid == 0) {
        int t = s_wsum[lane];
        int o = t;
        #pragma unroll
        for (int off = 1; off < 32; off <<= 1) {
            int u = __shfl_up_sync(0xffffffffu, t, off);
            if (lane >= off) t += u;
        }
        s_wsum[lane] = t - o;   // exclusive warp offsets
    }
    __syncthreads();
    int run = s_wsum[wid] + s - own;    // exclusive prefix for node n0

    g_rowptr[n0] = run;  s_base[n0] = run;
    float deg0 = (float)v0 + 2.0f;
    s_dinv[n0] = rsqrtf(deg0); g_selfnorm[n0] = 2.0f / deg0;
    int run1 = run + v0;
    g_rowptr[n1] = run1; s_base[n1] = run1;
    float deg1 = (float)v1 + 2.0f;
    s_dinv[n1] = rsqrtf(deg1); g_selfnorm[n1] = 2.0f / deg1;
    if (tid == 1023) g_rowptr[Ll] = run1 + v1;
    s_cnt[n0] = 0; s_cnt[n1] = 0;   // reuse as fill cursors
    __syncthreads();

    // fill CSR
    for (int e = tid; e < Ee; e += 1024) {
        int sN = (is64 ? (int)w[2 * e]        : (int)w[e])        & (Ll - 1);
        int d  = (is64 ? (int)w[2 * (Ee + e)] : (int)w[Ee + e])   & (Ll - 1);
        int pos = s_base[d] + atomicAdd(&s_cnt[d], 1);
        g_col[pos] = sN;
        g_enorm[pos] = s_dinv[sN] * s_dinv[d];
    }
}

// ---------------- pack weights into u64 k-pairs ----------------
__global__ void pack_weights(const float* __restrict__ W1,
                             const float* __restrict__ W2,
                             const float* __restrict__ W3) {
    int flat = blockIdx.x * blockDim.x + threadIdx.x;   // 0 .. 288*128-1
    const int N1 = (C0/2) * Cc;          // 4096
    const int N2 = (C2/2) * Cc;          // 16384
    if (flat < N1) {
        int kp = flat / Cc, c = flat % Cc;
        unsigned lo = __float_as_uint(W1[(2*kp)   * Cc + c]);
        unsigned hi = __float_as_uint(W1[(2*kp+1) * Cc + c]);
        g_Wp1[flat] = (ull)lo | ((ull)hi << 32);
    } else if (flat < N1 + N2) {
        int f = flat - N1;
        int kp = f / Cc, c = f % Cc;
        unsigned lo = __float_as_uint(W2[(2*kp)   * Cc + c]);
        unsigned hi = __float_as_uint(W2[(2*kp+1) * Cc + c]);
        g_Wp2[f] = (ull)lo | ((ull)hi << 32);
    } else if (flat < N1 + 2*N2) {
        int f = flat - N1 - N2;
        int kp = f / Cc, c = f % Cc;
        unsigned lo = __float_as_uint(W3[(2*kp)   * Cc + c]);
        unsigned hi = __float_as_uint(W3[(2*kp+1) * Cc + c]);
        g_Wp3[f] = (ull)lo | ((ull)hi << 32);
    }
}

// ---------------- transpose x [b,n,c,l] -> g_h0 [g,l,c] ----------------
__global__ void transpose_x(const float* __restrict__ x) {
    __shared__ float t[32][33];
    int g = blockIdx.z, c0 = blockIdx.y * 32, l0 = blockIdx.x * 32;
    int tx = threadIdx.x, ty = threadIdx.y;
    #pragma unroll
    for (int i = 0; i < 32; i += 8) {
        int c = c0 + ty + i, l = l0 + tx;
        t[ty + i][tx] = x[((size_t)(g * C0 + c)) * Ll + l];
    }
    __syncthreads();
    #pragma unroll
    for (int i = 0; i < 32; i += 8) {
        int l = l0 + ty + i, c = c0 + tx;
        g_h0[((size_t)g * Ll + l) * C0 + c] = t[tx][ty + i];
    }
}

// ---------------- GEMM: Y[row, :] = act(X[row, :]) @ W[K,128] (+U)(+bias) ----------------
// 2-column register blocking: 128 threads = 64 cols x 2 row-halves.
// Thread (c, h) computes cols {c, c+64} for rows [h*16, h*16+16) of the 32-row tile.
// HALF_OUT selects fp16 output (for the aggregation gather payload).
template <int K, bool ADD_U, bool ADD_BIAS, bool ACT, bool HALF_OUT>
__device__ __forceinline__ void gemm_body(
    const float* __restrict__ X, const ull* __restrict__ Wp,
    const float* __restrict__ bias, const float* __restrict__ U,
    const float* __restrict__ scale, const float* __restrict__ shift,
    float* __restrict__ Yf, __half* __restrict__ Yh)
{
    __shared__ __align__(16) float sX[32 * K];
    __shared__ float s_sc[K], s_sh[K];
    int tid = threadIdx.x;
    int c = tid & 63;          // column group
    int h = tid >> 6;          // row half (0/1)
    size_t row0 = (size_t)blockIdx.x * 32;

    if (ACT) {
        if (tid < K) { s_sc[tid] = scale[tid]; s_sh[tid] = shift[tid]; }
        __syncthreads();
    }

    const float4* Xv = (const float4*)(X + row0 * K);
    float4* sv = (float4*)sX;
    #pragma unroll
    for (int i = tid; i < 32 * K / 4; i += 128) {
        float4 v = Xv[i];
        if (ACT) {
            int cc = (i * 4) % K;
            v.x = fmaxf(0.f, fmaf(v.x, s_sc[cc + 0], s_sh[cc + 0]));
            v.y = fmaxf(0.f, fmaf(v.y, s_sc[cc + 1], s_sh[cc + 1]));
            v.z = fmaxf(0.f, fmaf(v.z, s_sc[cc + 2], s_sh[cc + 2]));
            v.w = fmaxf(0.f, fmaf(v.w, s_sc[cc + 3], s_sh[cc + 3]));
        }
        sv[i] = v;
    }
    __syncthreads();

    ull accA[16], accB[16];
    #pragma unroll
    for (int r = 0; r < 16; r++) { accA[r] = 0ull; accB[r] = 0ull; }

    const float* sXh = sX + (h * 16) * K;
    for (int kq = 0; kq < K / 4; kq++) {          // 4 k-values (= 2 k-pairs) per iter
        ull wA0 = Wp[(2 * kq)     * Cc + c];
        ull wA1 = Wp[(2 * kq + 1) * Cc + c];
        ull wB0 = Wp[(2 * kq)     * Cc + c + 64];
        ull wB1 = Wp[(2 * kq + 1) * Cc + c + 64];
        #pragma unroll
        for (int r = 0; r < 16; r++) {
            ulonglong2 xv = *(const ulonglong2*)(sXh + r * K + 4 * kq);
            FFMA2(accA[r], xv.x, wA0);
            FFMA2(accA[r], xv.y, wA1);
            FFMA2(accB[r], xv.x, wB0);
            FFMA2(accB[r], xv.y, wB1);
        }
    }

    float bvA = ADD_BIAS ? bias[c] : 0.f;
    float bvB = ADD_BIAS ? bias[c + 64] : 0.f;
    #pragma unroll
    for (int r = 0; r < 16; r++) {
        size_t row = row0 + h * 16 + r;
        float vA = __uint_as_float((unsigned)accA[r]) + __uint_as_float((unsigned)(accA[r] >> 32)) + bvA;
        float vB = __uint_as_float((unsigned)accB[r]) + __uint_as_float((unsigned)(accB[r] >> 32)) + bvB;
        if (ADD_U) {
            size_t l = row % Ll;
            size_t b = row / ((size_t)Nn * Ll);
            const float* Up = U + (b * Ll + l) * Cc;
            vA += Up[c];
            vB += Up[c + 64];
        }
        if (HALF_OUT) {
            Yh[row * Cc + c]      = __float2half(vA);
            Yh[row * Cc + c + 64] = __float2half(vB);
        } else {
            Yf[row * Cc + c]      = vA;
            Yf[row * Cc + c + 64] = vB;
        }
    }
}

__global__ __launch_bounds__(128) void gemm1_kernel(const float* __restrict__ bias) {
    // block 0 zeroes the BN stat accumulators for this layer
    if (blockIdx.x == 0) {
        g_sum[threadIdx.x] = 0.0;       g_sumsq[threadIdx.x] = 0.0;
        g_sum[Cc + threadIdx.x] = 0.0;  g_sumsq[Cc + threadIdx.x] = 0.0;
    }
    gemm_body<C0, false, true, false, false>(g_agg0, g_Wp1, bias, nullptr, nullptr, nullptr, g_a, nullptr);
}
// U = relu(bn(amax)) @ W_up      (upper-half BN params: offset Cc)
__global__ __launch_bounds__(128) void gemmU_kernel(int wsel) {
    const ull* wp = ((wsel == 2) ? g_Wp2 : g_Wp3) + (Cc / 2) * Cc;
    gemm_body<Cc, false, false, true, false>(g_amax, wp, nullptr, nullptr, g_scale + Cc, g_shift + Cc, g_U, nullptr);
}
// hW = relu(bn(a)) @ W_low + U[b]  -> fp16 output for the gather
__global__ __launch_bounds__(128) void gemmM_kernel(int wsel) {
    const ull* wp = (wsel == 2) ? g_Wp2 : g_Wp3;
    gemm_body<Cc, true, false, true, true>(g_a, wp, nullptr, g_U, g_scale, g_shift, nullptr, g_hWh);
}

// ---------------- aggregation (fp32 payload, 64ch: layer 1) ----------------
__global__ __launch_bounds__(128) void agg1_kernel() {
    constexpr int TPN = C0 / 4;   // 16
    constexpr int NPB = 128 / TPN;
    int lane = threadIdx.x % TPN;
    int nidx = threadIdx.x / TPN;
    size_t ng = (size_t)blockIdx.x * NPB + nidx;
    int node = (int)(ng % Ll);
    size_t g = ng / Ll;
    const float4* Xg = (const float4*)(g_h0 + g * Ll * C0);

    float sn = g_selfnorm[node];
    float4 xv = Xg[(size_t)node * TPN + lane];
    float4 acc = make_float4(sn * xv.x, sn * xv.y, sn * xv.z, sn * xv.w);

    int s = g_rowptr[node], e = g_rowptr[node + 1];
    for (int i = s; i < e; i++) {
        float nw = g_enorm[i];
        float4 v = Xg[(size_t)g_col[i] * TPN + lane];
        acc.x += nw * v.x; acc.y += nw * v.y; acc.z += nw * v.z; acc.w += nw * v.w;
    }
    ((float4*)g_agg0)[ng * TPN + lane] = acc;
}

// ---------------- aggregation (fp16 payload, 128ch: layers 2/3) ----------------
// 32 threads per node, each handles 4 channels via uint2 (2 half2); writes fp32.
__global__ __launch_bounds__(128) void agg2_kernel(const float* __restrict__ bias) {
    if (blockIdx.x == 0) {     // zero BN accumulators for this layer
        int t = threadIdx.x;
        g_sum[t] = 0.0;       g_sumsq[t] = 0.0;
        g_sum[Cc + t] = 0.0;  g_sumsq[Cc + t] = 0.0;
    }
    const int TPN = 32;
    int lane = threadIdx.x & 31;
    int nidx = threadIdx.x >> 5;
    size_t ng = (size_t)blockIdx.x * 4 + nidx;
    int node = (int)(ng % Ll);
    size_t g = ng / Ll;
    const uint2* Xg = (const uint2*)(g_hWh + g * Ll * Cc);

    float sn = g_selfnorm[node];
    uint2 hv = Xg[(size_t)node * TPN + lane];
    float2 f0 = __half22float2(*(const __half2*)&hv.x);
    float2 f1 = __half22float2(*(const __half2*)&hv.y);
    float4 acc = make_float4(sn * f0.x, sn * f0.y, sn * f1.x, sn * f1.y);

    int s = g_rowptr[node], e = g_rowptr[node + 1];
    for (int i = s; i < e; i++) {
        float nw = g_enorm[i];
        uint2 v = Xg[(size_t)g_col[i] * TPN + lane];
        float2 a0 = __half22float2(*(const __half2*)&v.x);
        float2 a1 = __half22float2(*(const __half2*)&v.y);
        acc.x += nw * a0.x; acc.y += nw * a0.y; acc.z += nw * a1.x; acc.w += nw * a1.y;
    }
    float4 bv = ((const float4*)bias)[lane];
    acc.x += bv.x; acc.y += bv.y; acc.z += bv.z; acc.w += bv.w;
    ((float4*)g_a)[ng * TPN + lane] = acc;
}

// ---------------- fused amax + BN stats: ONE pass over g_a ----------------
__global__ void amax_stats_kernel() {
    int c = threadIdx.x;
    float s_a = 0.f, ss_a = 0.f, s_m = 0.f, ss_m = 0.f;
    size_t base = (size_t)blockIdx.x * 8;
    #pragma unroll 1
    for (int j = 0; j < 8; j++) {
        size_t bl = base + j;                 // over B*L = 8192
        size_t b = bl / Ll, l = bl % Ll;
        const float* p = g_a + ((b * Nn) * Ll + l) * Cc + c;
        float m = -3.4e38f;
        #pragma unroll
        for (int n = 0; n < Nn; n++) {
            float v = p[(size_t)n * Ll * Cc];
            s_a += v; ss_a += v * v;
            m = fmaxf(m, v);
        }
        g_amax[bl * Cc + c] = m;
        s_m += m; ss_m += m * m;
    }
    atomicAdd(&g_sum[c],        (double)s_a);
    atomicAdd(&g_sumsq[c],      (double)ss_a);
    atomicAdd(&g_sum[Cc + c],   (double)s_m);
    atomicAdd(&g_sumsq[Cc + c], (double)ss_m);
}

__global__ void bn_kernel(const float* __restrict__ gamma, const float* __restrict__ beta) {
    int c = threadIdx.x;                       // 256
    double cnt = (c < Cc) ? (double)((size_t)Gg * Ll) : (double)((size_t)Bb * Ll);
    double mean = g_sum[c] / cnt;
    double var  = g_sumsq[c] / cnt - mean * mean;
    double inv  = 1.0 / sqrt(var + (double)EPSf);
    double sc   = (double)gamma[c] * inv;
    g_scale[c] = (float)sc;
    g_shift[c] = (float)((double)beta[c] - mean * sc);
}

// ---------------- final: BN+relu+concat+transpose to out [g, 256, l] ----------------
__global__ void final_kernel(float* __restrict__ out) {
    __shared__ float t[32][33];
    int g = blockIdx.z, c0 = blockIdx.y * 32, l0 = blockIdx.x * 32;
    int tx = threadIdx.x, ty = threadIdx.y;
    #pragma unroll
    for (int i = 0; i < 32; i += 8) {
        int l = l0 + ty + i;
        int c = c0 + tx;
        float v;
        if (c < Cc) v = g_a[((size_t)g * Ll + l) * Cc + c];
        else        v = g_amax[((size_t)(g / Nn) * Ll + l) * Cc + (c - Cc)];
        v = fmaxf(0.f, fmaf(v, g_scale[c], g_shift[c]));
        t[ty + i][tx] = v;
    }
    __syncthreads();
    #pragma unroll
    for (int i = 0; i < 32; i += 8) {
        int c = c0 + ty + i;
        int l = l0 + tx;
        out[((size_t)g * C2 + c) * Ll + l] = t[tx][ty + i];
    }
}

// ---------------- launch ----------------
extern "C" void kernel_launch(void* const* d_in, const int* in_sizes, int n_in,
                              void* d_out, int out_size) {
    const float* x  = (const float*)d_in[0];
    const void*  ei = d_in[1];   // int32 or int64, detected on device
    const float *W1 = (const float*)d_in[2],  *b1  = (const float*)d_in[3];
    const float *W2 = (const float*)d_in[4],  *b2  = (const float*)d_in[5];
    const float *W3 = (const float*)d_in[6],  *b3  = (const float*)d_in[7];
    const float *ga1 = (const float*)d_in[8],  *be1 = (const float*)d_in[9];
    const float *ga2 = (const float*)d_in[10], *be2 = (const float*)d_in[11];
    const float *ga3 = (const float*)d_in[12], *be3 = (const float*)d_in[13];
    float* out = (float*)d_out;

    const int rowsGL = Gg * Ll;   // 131072
    const int rowsBL = Bb * Ll;   // 8192

    // setup (launch idx 0..2)
    graph_build<<<1, 1024>>>((const unsigned int*)ei);
    pack_weights<<<(288 * 128 + 255) / 256, 256>>>(W1, W2, W3);
    transpose_x<<<dim3(Ll / 32, C0 / 32, Gg), dim3(32, 8)>>>(x);

    // ---- layer 1:  a = (A h0) W1 + b1 ----   (agg1 = launch idx 3 -> ncu capture)
    agg1_kernel<<<rowsGL / 8, 128>>>();
    gemm1_kernel<<<rowsGL / 32, 128>>>(b1);       // also zeroes BN accumulators
    amax_stats_kernel<<<rowsBL / 8, 128>>>();
    bn_kernel<<<1, C2>>>(ga1, be1);

    // ---- layer 2 ----
    gemmU_kernel<<<rowsBL / 32, 128>>>(2);
    gemmM_kernel<<<rowsGL / 32, 128>>>(2);
    agg2_kernel<<<rowsGL / 4, 128>>>(b2);         // also zeroes BN accumulators
    amax_stats_kernel<<<rowsBL / 8, 128>>>();
    bn_kernel<<<1, C2>>>(ga2, be2);

    // ---- layer 3 ----
    gemmU_kernel<<<rowsBL / 32, 128>>>(3);
    gemmM_kernel<<<rowsGL / 32, 128>>>(3);
    agg2_kernel<<<rowsGL / 4, 128>>>(b3);
    amax_stats_kernel<<<rowsBL / 8, 128>>>();
    bn_kernel<<<1, C2>>>(ga3, be3);

    // fused BN + relu + concat + transpose into output layout [b*n, 256, l]
    final_kernel<<<dim3(Ll / 32, C2 / 32, Gg), dim3(32, 8)>>>(out);
}